// round 8
// baseline (speedup 1.0000x reference)
#include <cuda_runtime.h>
#include <cuda_bf16.h>
#include <cstdint>

// Problem constants
#define E_  8
#define H_  1024
#define F_  4096
#define T_  16384
#define TPE 2048   // tokens per expert

// ---------------- device scratch (static, allocation-free) ----------------
__device__ float g_inter[(size_t)E_ * TPE * F_]; // 256 MB, gelu(X@W1) fp32

// ---------------- helpers ----------------
__device__ __forceinline__ uint32_t tf32u(float x) {   // round-to-nearest tf32, as raw bits
    uint32_t u;
    asm("cvt.rna.tf32.f32 %0, %1;" : "=r"(u) : "f"(x));
    return u;
}

#define SMEM_SWZ(off) ((off) ^ (((off) >> 3) & 0x70))

__device__ __forceinline__ void cp_async16(uint32_t sm, const void* g) {
    asm volatile("cp.async.cg.shared.global [%0], [%1], 16;" :: "r"(sm), "l"(g));
}
#define CP_COMMIT()   asm volatile("cp.async.commit_group;" ::: "memory")
#define CP_WAIT_1()   asm volatile("cp.async.wait_group 1;" ::: "memory")
#define CP_WAIT_0()   asm volatile("cp.async.wait_group 0;" ::: "memory")

__device__ __forceinline__ uint32_t smem_u32(const void* p) {
    uint32_t a;
    asm("{ .reg .u64 t; cvta.to.shared.u64 t, %1; cvt.u32.u64 %0, t; }" : "=r"(a) : "l"(p));
    return a;
}

__device__ __forceinline__ float lds_f32(uint32_t addr) {
    float v;
    asm volatile("ld.shared.f32 %0, [%1];" : "=f"(v) : "r"(addr));
    return v;
}

// mma.sync m16n8k8 tf32 (portable PTX, lowers to legacy HMMA on sm_103)
__device__ __forceinline__ void mma_tf32(float* d,
                                         uint32_t a0, uint32_t a1, uint32_t a2, uint32_t a3,
                                         uint32_t b0, uint32_t b1) {
    asm volatile(
        "mma.sync.aligned.m16n8k8.row.col.f32.tf32.tf32.f32 "
        "{%0,%1,%2,%3}, {%4,%5,%6,%7}, {%8,%9}, {%0,%1,%2,%3};"
        : "+f"(d[0]), "+f"(d[1]), "+f"(d[2]), "+f"(d[3])
        : "r"(a0), "r"(a1), "r"(a2), "r"(a3), "r"(b0), "r"(b1));
}

__device__ __forceinline__ float gelu_tanh(float x) {
    float u = 0.7978845608028654f * (x + 0.044715f * x * x * x);
    float au = fabsf(u);
    float e = __expf(-2.0f * au);
    float t = (1.0f - e) * __frcp_rn(1.0f + e);
    t = copysignf(t, u);
    return 0.5f * x * (1.0f + t);
}

// ---------------- mma.sync tf32 GEMM, zero-prep operand paths ----------------
// C[M,N] = round_tf32(A) . round_tf32(B) with A K-major [m][k] and B N-major
// [k][n] (native layouts of x / W1 / W2 -> no transpose or rounding prep).
// CTA tile 128x128, 128 threads, warp grid 2x2, warp tile 64x64.
// A slab: 128 rows x 128B, SW128 swizzle. B slab: 32 k-rows x 512B with
// per-k XOR swizzle ((k&7)<<4) -> fragment reads are <=2-way conflicted.
// cvt.rna.tf32 applied to every fragment word (bit-identical to prep version).
#define STAGES      3
#define STAGE_BYTES 32768            // 16KB A + 16KB B per 32-K slab
#define GEMM_SMEM   (STAGES * STAGE_BYTES)

template <bool GELU>
__global__ __launch_bounds__(128, 2) void gemm_mma_kernel(
    const float* __restrict__ A, const float* __restrict__ B, float* __restrict__ C,
    int lda, int ldb, int ldc,
    long sAe, long sBe, long sCe, int KT)
{
    extern __shared__ char smem[];
    uint32_t sb = smem_u32(smem);
    int tid = threadIdx.x;
    int lane = tid & 31, wid = tid >> 5;
    int g = lane >> 2, tig = lane & 3;
    int wm = wid & 1, wn = wid >> 1;
    int nt = blockIdx.x, mt = blockIdx.y, e = blockIdx.z;

    const float* Abase = A + (long)e * sAe + (long)mt * 128 * lda;
    const float* Bbase = B + (long)e * sBe + (long)nt * 128;   // n-offset into N-major B

    // per-stage loader
    auto load_stage = [&](int stg, int kt) {
        uint32_t sA = sb + stg * STAGE_BYTES;
        uint32_t sB = sA + 16384;
        const float* ga = Abase + kt * 32;
        const float* gb = Bbase + (long)kt * 32 * ldb;
        // A: 128 rows x 128B, SW128
#pragma unroll
        for (int i = 0; i < 8; i++) {
            int id = tid + i * 128;
            int row = id >> 3;
            int c = (id & 7) * 16;
            cp_async16(sA + SMEM_SWZ(row * 128 + c), (const char*)(ga + (long)row * lda) + c);
        }
        // B: 32 k-rows x 512B (128 n-floats), per-k XOR swizzle on 16B units
#pragma unroll
        for (int i = 0; i < 8; i++) {
            int id = tid + i * 128;
            int k = id >> 5;
            int c = (id & 31) * 16;
            cp_async16(sB + k * 512 + (c ^ ((k & 7) << 4)),
                       (const char*)(gb + (long)k * ldb) + c);
        }
    };

    // A fragment addressing (rows == g mod 8 -> single XOR key g<<4)
    uint32_t key = (uint32_t)(g << 4);
    uint32_t aOff[4][2];   // [m-atom][half]
#pragma unroll
    for (int i = 0; i < 4; i++)
#pragma unroll
        for (int h = 0; h < 2; h++)
            aOff[i][h] = (uint32_t)((wm * 64 + i * 16 + h * 8 + g) * 128);

    // B fragment addressing in N-major slab: element (n, k) at k*512 + (n*4 ^ ((k&7)<<4)).
    // b0: k = j*8 + tig ; b1: k = j*8 + tig + 4. Per-j advance = 8 rows = 4096B.
    uint32_t b0Off[8], b1Off[8];
#pragma unroll
    for (int nn = 0; nn < 8; nn++) {
        uint32_t n4 = (uint32_t)((wn * 64 + nn * 8 + g) * 4);
        b0Off[nn] = 16384u + (uint32_t)tig * 512 + (n4 ^ ((uint32_t)tig << 4));
        b1Off[nn] = 16384u + (uint32_t)(tig + 4) * 512 + (n4 ^ ((uint32_t)(tig + 4) << 4));
    }

    float acc[4][8][4];
#pragma unroll
    for (int i = 0; i < 4; i++)
#pragma unroll
        for (int nn = 0; nn < 8; nn++)
#pragma unroll
            for (int r = 0; r < 4; r++) acc[i][nn][r] = 0.0f;

    // prologue: 2 slabs in flight
    load_stage(0, 0); CP_COMMIT();
    load_stage(1, 1); CP_COMMIT();

    int cur = 0, nxs = 2;
    for (int kt = 0; kt < KT; kt++) {
        if (kt < KT - 1) { CP_WAIT_1(); } else { CP_WAIT_0(); }
        __syncthreads();   // slab kt resident; buffer `nxs` fully consumed

        int nx = kt + 2;
        if (nx < KT) {
            load_stage(nxs, nx);
            CP_COMMIT();
        }

        uint32_t stg = sb + (uint32_t)cur * STAGE_BYTES;
#pragma unroll
        for (int j = 0; j < 4; j++) {
            uint32_t cb0 = (uint32_t)(j * 32 + tig * 4) ^ key;
            uint32_t cb1 = (uint32_t)(j * 32 + tig * 4 + 16) ^ key;
            uint32_t bj = (uint32_t)(j * 4096);

            uint32_t af[4][4];
#pragma unroll
            for (int i = 0; i < 4; i++) {
                af[i][0] = tf32u(lds_f32(stg + aOff[i][0] + cb0));
                af[i][1] = tf32u(lds_f32(stg + aOff[i][1] + cb0));
                af[i][2] = tf32u(lds_f32(stg + aOff[i][0] + cb1));
                af[i][3] = tf32u(lds_f32(stg + aOff[i][1] + cb1));
            }
            uint32_t bf[8][2];
#pragma unroll
            for (int nn = 0; nn < 8; nn++) {
                bf[nn][0] = tf32u(lds_f32(stg + bj + b0Off[nn]));
                bf[nn][1] = tf32u(lds_f32(stg + bj + b1Off[nn]));
            }
#pragma unroll
            for (int i = 0; i < 4; i++)
#pragma unroll
                for (int nn = 0; nn < 8; nn++)
                    mma_tf32(acc[i][nn], af[i][0], af[i][1], af[i][2], af[i][3],
                             bf[nn][0], bf[nn][1]);
        }

        cur = cur + 1 == STAGES ? 0 : cur + 1;
        nxs = nxs + 1 == STAGES ? 0 : nxs + 1;
    }

    // ---- epilogue: (gelu) -> direct STG.64, 32B-coalesced.
    // No tf32 rounding needed here: GEMM2 rounds its A fragments on load.
    float* Cbase = C + (long)e * sCe + (long)mt * 128 * ldc + (long)nt * 128;
#pragma unroll
    for (int i = 0; i < 4; i++) {
        int r0 = wm * 64 + i * 16 + g;
#pragma unroll
        for (int nn = 0; nn < 8; nn++) {
            int col = wn * 64 + nn * 8 + 2 * tig;
            float v0 = acc[i][nn][0], v1 = acc[i][nn][1];
            float v2 = acc[i][nn][2], v3 = acc[i][nn][3];
            if (GELU) {
                v0 = gelu_tanh(v0); v1 = gelu_tanh(v1);
                v2 = gelu_tanh(v2); v3 = gelu_tanh(v3);
            }
            *(float2*)(Cbase + (long)r0 * ldc + col)       = make_float2(v0, v1);
            *(float2*)(Cbase + (long)(r0 + 8) * ldc + col) = make_float2(v2, v3);
        }
    }
}

// ---------------- launch ----------------
extern "C" void kernel_launch(void* const* d_in, const int* in_sizes, int n_in,
                              void* d_out, int out_size)
{
    const float* x  = (const float*)d_in[0];
    const float* w1 = (const float*)d_in[1];
    const float* w2 = (const float*)d_in[2];
    float* out = (float*)d_out;

    float* inter;
    cudaGetSymbolAddress((void**)&inter, g_inter);

    cudaFuncSetAttribute(gemm_mma_kernel<true>,
                         cudaFuncAttributeMaxDynamicSharedMemorySize, GEMM_SMEM);
    cudaFuncSetAttribute(gemm_mma_kernel<false>,
                         cudaFuncAttributeMaxDynamicSharedMemorySize, GEMM_SMEM);
    cudaFuncSetAttribute(gemm_mma_kernel<true>,
                         cudaFuncAttributePreferredSharedMemoryCarveout, 100);
    cudaFuncSetAttribute(gemm_mma_kernel<false>,
                         cudaFuncAttributePreferredSharedMemoryCarveout, 100);

    // GEMM1: inter = gelu(X @ W1)   A = x [t][h] K-major, B = W1 [h][f] N-major
    gemm_mma_kernel<true><<<dim3(F_ / 128, TPE / 128, E_), 128, GEMM_SMEM>>>(
        x, w1, inter,
        H_, F_, F_,
        (long)TPE * H_, (long)H_ * F_, (long)TPE * F_,
        H_ / 32);

    // GEMM2: out = inter @ W2       A = inter [t][f] K-major, B = W2 [f][h] N-major
    gemm_mma_kernel<false><<<dim3(H_ / 128, TPE / 128, E_), 128, GEMM_SMEM>>>(
        inter, w2, out,
        F_, H_, H_,
        (long)TPE * F_, (long)F_ * H_, (long)TPE * H_,
        F_ / 32);
}

// round 12
// speedup vs baseline: 1.0467x; 1.0467x over previous
#include <cuda_runtime.h>
#include <cuda_bf16.h>
#include <cstdint>

// Problem constants
#define E_  8
#define H_  1024
#define F_  4096
#define T_  16384
#define TPE 2048   // tokens per expert

// ---------------- device scratch (static, allocation-free) ----------------
__device__ float g_xr  [(size_t)T_ * H_];        //  64 MB, RNA-rounded X
__device__ float g_w1t [(size_t)E_ * F_ * H_];   // 128 MB, W1^T per expert [E,F,H]
__device__ float g_w2t [(size_t)E_ * H_ * F_];   // 128 MB, W2^T per expert [E,H,F]
__device__ float g_inter[(size_t)E_ * TPE * F_]; // 256 MB, gelu(X@W1), tf32-rounded

// ---------------- helpers ----------------
__device__ __forceinline__ float tf32r(float x) {
    uint32_t u;
    asm("cvt.rna.tf32.f32 %0, %1;" : "=r"(u) : "f"(x));
    return __uint_as_float(u);
}

#define SMEM_SWZ(off) ((off) ^ (((off) >> 3) & 0x70))

__device__ __forceinline__ void cp_async16(uint32_t sm, const void* g) {
    asm volatile("cp.async.cg.shared.global [%0], [%1], 16;" :: "r"(sm), "l"(g));
}
#define CP_COMMIT()   asm volatile("cp.async.commit_group;" ::: "memory")
#define CP_WAIT_1()   asm volatile("cp.async.wait_group 1;" ::: "memory")
#define CP_WAIT_0()   asm volatile("cp.async.wait_group 0;" ::: "memory")

__device__ __forceinline__ uint32_t smem_u32(const void* p) {
    uint32_t a;
    asm("{ .reg .u64 t; cvta.to.shared.u64 t, %1; cvt.u32.u64 %0, t; }" : "=r"(a) : "l"(p));
    return a;
}

__device__ __forceinline__ float lds_f32(uint32_t addr) {
    float v;
    asm volatile("ld.shared.f32 %0, [%1];" : "=f"(v) : "r"(addr));
    return v;
}

// mma.sync m16n8k8 tf32 (portable PTX, lowers to legacy HMMA on sm_103)
__device__ __forceinline__ void mma_tf32(float* d,
                                         uint32_t a0, uint32_t a1, uint32_t a2, uint32_t a3,
                                         uint32_t b0, uint32_t b1) {
    asm volatile(
        "mma.sync.aligned.m16n8k8.row.col.f32.tf32.tf32.f32 "
        "{%0,%1,%2,%3}, {%4,%5,%6,%7}, {%8,%9}, {%0,%1,%2,%3};"
        : "+f"(d[0]), "+f"(d[1]), "+f"(d[2]), "+f"(d[3])
        : "r"(a0), "r"(a1), "r"(a2), "r"(a3), "r"(b0), "r"(b1));
}

__device__ __forceinline__ float gelu_tanh(float x) {
    float u = 0.7978845608028654f * (x + 0.044715f * x * x * x);
    float au = fabsf(u);
    float e = __expf(-2.0f * au);
    float t = (1.0f - e) * __frcp_rn(1.0f + e);
    t = copysignf(t, u);
    return 0.5f * x * (1.0f + t);
}

// ---------------- prep kernels ----------------
__global__ void round_x_kernel(const float4* __restrict__ x, float4* __restrict__ o, int n4) {
    int i = blockIdx.x * blockDim.x + threadIdx.x;
    if (i < n4) {
        float4 v = x[i];
        v.x = tf32r(v.x); v.y = tf32r(v.y); v.z = tf32r(v.z); v.w = tf32r(v.w);
        o[i] = v;
    }
}

// W [E][R][C] -> WT [E][C][R], fused RNA rounding. block (32,8), grid (C/32, R/32, E)
__global__ void transpose_rna_kernel(const float* __restrict__ W, float* __restrict__ WT,
                                     int R, int C) {
    __shared__ float t[32][33];
    int e = blockIdx.z;
    const float* Wb = W + (size_t)e * R * C;
    float* Tb = WT + (size_t)e * R * C;
    int c0 = blockIdx.x * 32, r0 = blockIdx.y * 32;
    int tx = threadIdx.x, ty = threadIdx.y;
#pragma unroll
    for (int i = 0; i < 32; i += 8)
        t[ty + i][tx] = tf32r(Wb[(size_t)(r0 + ty + i) * C + c0 + tx]);
    __syncthreads();
#pragma unroll
    for (int i = 0; i < 32; i += 8)
        Tb[(size_t)(c0 + ty + i) * R + r0 + tx] = t[tx][ty + i];
}

// ---------------- mma.sync tf32 GEMM: C[M,N] = A(K-major) . B(K-major)^T ----------------
// CTA tile 128x128, 128 threads, warp grid 2x2, warp tile 64x64.
// Schedule (volatile asm -> program order == issue order):
//  - B fragments double-buffered in registers across the 4 k8-phases
//  - A fragments loaded as 4-LDS quads immediately before each 8-MMA burst
//  - next slab's cp.async burst issued once, AFTER phase 0's MMA block
//    (its ~128 issue cycles hide under phases 1-3 instead of head-of-slab)
// 3 stages x 32KB = 96KB smem, 2 CTAs/SM.
#define STAGES      3
#define STAGE_BYTES 32768            // 16KB A + 16KB B per 32-K slab
#define GEMM_SMEM   (STAGES * STAGE_BYTES)

template <bool GELU>
__global__ __launch_bounds__(128, 2) void gemm_mma_kernel(
    const float* __restrict__ A, const float* __restrict__ B, float* __restrict__ C,
    int lda, int ldb, int ldc,
    long sAe, long sBe, long sCe, int KT)
{
    extern __shared__ char smem[];
    uint32_t sb = smem_u32(smem);
    int tid = threadIdx.x;
    int lane = tid & 31, wid = tid >> 5;
    int g = lane >> 2, tig = lane & 3;
    int wm = wid & 1, wn = wid >> 1;
    int nt = blockIdx.x, mt = blockIdx.y, e = blockIdx.z;

    const float* Abase = A + (long)e * sAe + (long)mt * 128 * lda;
    const float* Bbase = B + (long)e * sBe + (long)nt * 128 * ldb;

    // slab loader: 128 rows x 128B per operand, SW128 swizzle (single call site shape
    // identical to the proven round-6 kernel)
    auto load_stage = [&](int stg, int kt) {
        uint32_t sA = sb + stg * STAGE_BYTES;
        uint32_t sB = sA + 16384;
        const float* ga = Abase + kt * 32;
        const float* gb = Bbase + kt * 32;
#pragma unroll
        for (int i = 0; i < 8; i++) {
            int id = tid + i * 128;
            int row = id >> 3;
            int c = (id & 7) * 16;
            cp_async16(sA + SMEM_SWZ(row * 128 + c), (const char*)(ga + (long)row * lda) + c);
        }
#pragma unroll
        for (int i = 0; i < 8; i++) {
            int id = tid + i * 128;
            int row = id >> 3;
            int c = (id & 7) * 16;
            cp_async16(sB + SMEM_SWZ(row * 128 + c), (const char*)(gb + (long)row * ldb) + c);
        }
    };

    // fragment addressing: all rows == g (mod 8) -> single XOR key g<<4
    uint32_t key = (uint32_t)(g << 4);
    uint32_t aOff[4][2];   // [m-atom][half]
#pragma unroll
    for (int i = 0; i < 4; i++)
#pragma unroll
        for (int h = 0; h < 2; h++)
            aOff[i][h] = (uint32_t)((wm * 64 + i * 16 + h * 8 + g) * 128);
    uint32_t bOff[8];      // [n-atom]
#pragma unroll
    for (int nn = 0; nn < 8; nn++)
        bOff[nn] = (uint32_t)(16384 + (wn * 64 + nn * 8 + g) * 128);

    float acc[4][8][4];
#pragma unroll
    for (int i = 0; i < 4; i++)
#pragma unroll
        for (int nn = 0; nn < 8; nn++)
#pragma unroll
            for (int r = 0; r < 4; r++) acc[i][nn][r] = 0.0f;

    // prologue: 2 slabs in flight
    load_stage(0, 0); CP_COMMIT();
    load_stage(1, 1); CP_COMMIT();

    int cur = 0, nxs = 2;
    for (int kt = 0; kt < KT; kt++) {
        if (kt < KT - 1) { CP_WAIT_1(); } else { CP_WAIT_0(); }
        __syncthreads();   // slab kt resident; buffer `nxs` fully consumed

        bool pf = (kt + 2 < KT);
        uint32_t stg = sb + (uint32_t)cur * STAGE_BYTES;

        uint32_t bf[2][16];
        // preload B fragments for phase 0
        {
            uint32_t cb0 = (uint32_t)(tig * 4) ^ key;
            uint32_t cb1 = (uint32_t)(tig * 4 + 16) ^ key;
#pragma unroll
            for (int nn = 0; nn < 8; nn++) {
                bf[0][2 * nn]     = __float_as_uint(lds_f32(stg + bOff[nn] + cb0));
                bf[0][2 * nn + 1] = __float_as_uint(lds_f32(stg + bOff[nn] + cb1));
            }
        }

#pragma unroll
        for (int j = 0; j < 4; j++) {
            uint32_t cb0 = (uint32_t)(j * 32 + tig * 4) ^ key;
            uint32_t cb1 = (uint32_t)(j * 32 + tig * 4 + 16) ^ key;

            // phase j compute: 4 x (A-quad LDS + 8 MMAs)
#pragma unroll
            for (int i = 0; i < 4; i++) {
                uint32_t a0 = __float_as_uint(lds_f32(stg + aOff[i][0] + cb0));
                uint32_t a1 = __float_as_uint(lds_f32(stg + aOff[i][1] + cb0));
                uint32_t a2 = __float_as_uint(lds_f32(stg + aOff[i][0] + cb1));
                uint32_t a3 = __float_as_uint(lds_f32(stg + aOff[i][1] + cb1));
#pragma unroll
                for (int nn = 0; nn < 8; nn++)
                    mma_tf32(acc[i][nn], a0, a1, a2, a3,
                             bf[j & 1][2 * nn], bf[j & 1][2 * nn + 1]);
            }

            // after phase 0's MMAs: issue next slab's cp.async burst
            // (hides under phases 1-3's tensor work)
            if (j == 0 && pf) {
                load_stage(nxs, kt + 2);
                CP_COMMIT();
            }

            // preload next phase's B fragments under this phase's MMA tail
            if (j < 3) {
                uint32_t nb0 = (uint32_t)((j + 1) * 32 + tig * 4) ^ key;
                uint32_t nb1 = (uint32_t)((j + 1) * 32 + tig * 4 + 16) ^ key;
#pragma unroll
                for (int nn = 0; nn < 8; nn++) {
                    bf[(j + 1) & 1][2 * nn]     = __float_as_uint(lds_f32(stg + bOff[nn] + nb0));
                    bf[(j + 1) & 1][2 * nn + 1] = __float_as_uint(lds_f32(stg + bOff[nn] + nb1));
                }
            }
        }

        cur = cur + 1 == STAGES ? 0 : cur + 1;
        nxs = nxs + 1 == STAGES ? 0 : nxs + 1;
    }

    // ---- epilogue: (gelu + tf32-round) -> direct STG.64, 32B-coalesced
    float* Cbase = C + (long)e * sCe + (long)mt * 128 * ldc + (long)nt * 128;
#pragma unroll
    for (int i = 0; i < 4; i++) {
        int r0 = wm * 64 + i * 16 + g;
#pragma unroll
        for (int nn = 0; nn < 8; nn++) {
            int col = wn * 64 + nn * 8 + 2 * tig;
            float v0 = acc[i][nn][0], v1 = acc[i][nn][1];
            float v2 = acc[i][nn][2], v3 = acc[i][nn][3];
            if (GELU) {
                v0 = tf32r(gelu_tanh(v0)); v1 = tf32r(gelu_tanh(v1));
                v2 = tf32r(gelu_tanh(v2)); v3 = tf32r(gelu_tanh(v3));
            }
            *(float2*)(Cbase + (long)r0 * ldc + col)       = make_float2(v0, v1);
            *(float2*)(Cbase + (long)(r0 + 8) * ldc + col) = make_float2(v2, v3);
        }
    }
}

// ---------------- launch ----------------
extern "C" void kernel_launch(void* const* d_in, const int* in_sizes, int n_in,
                              void* d_out, int out_size)
{
    const float* x  = (const float*)d_in[0];
    const float* w1 = (const float*)d_in[1];
    const float* w2 = (const float*)d_in[2];
    float* out = (float*)d_out;

    float *xr, *w1t, *w2t, *inter;
    cudaGetSymbolAddress((void**)&xr,    g_xr);
    cudaGetSymbolAddress((void**)&w1t,   g_w1t);
    cudaGetSymbolAddress((void**)&w2t,   g_w2t);
    cudaGetSymbolAddress((void**)&inter, g_inter);

    cudaFuncSetAttribute(gemm_mma_kernel<true>,
                         cudaFuncAttributeMaxDynamicSharedMemorySize, GEMM_SMEM);
    cudaFuncSetAttribute(gemm_mma_kernel<false>,
                         cudaFuncAttributeMaxDynamicSharedMemorySize, GEMM_SMEM);
    cudaFuncSetAttribute(gemm_mma_kernel<true>,
                         cudaFuncAttributePreferredSharedMemoryCarveout, 100);
    cudaFuncSetAttribute(gemm_mma_kernel<false>,
                         cudaFuncAttributePreferredSharedMemoryCarveout, 100);

    // 1) RNA-round X to tf32 grid
    {
        int n4 = T_ * H_ / 4;
        round_x_kernel<<<n4 / 256, 256>>>((const float4*)x, (float4*)xr, n4);
    }
    // 2) transpose + round weights: W1[E,H,F] -> [E,F,H]; W2[E,F,H] -> [E,H,F]
    transpose_rna_kernel<<<dim3(F_ / 32, H_ / 32, E_), dim3(32, 8)>>>(w1, w1t, H_, F_);
    transpose_rna_kernel<<<dim3(H_ / 32, F_ / 32, E_), dim3(32, 8)>>>(w2, w2t, F_, H_);

    // 3) GEMM1: inter = gelu(X @ W1)   (M=2048, N=4096, K=1024 per expert)
    gemm_mma_kernel<true><<<dim3(F_ / 128, TPE / 128, E_), 128, GEMM_SMEM>>>(
        xr, w1t, inter,
        H_, H_, F_,
        (long)TPE * H_, (long)F_ * H_, (long)TPE * F_,
        H_ / 32);

    // 4) GEMM2: out = inter @ W2       (M=2048, N=1024, K=4096 per expert)
    gemm_mma_kernel<false><<<dim3(H_ / 128, TPE / 128, E_), 128, GEMM_SMEM>>>(
        inter, w2t, out,
        F_, F_, H_,
        (long)TPE * F_, (long)H_ * F_, (long)TPE * H_,
        F_ / 32);
}